// round 13
// baseline (speedup 1.0000x reference)
#include <cuda_runtime.h>
#include <cuda_bf16.h>
#include <math.h>

#define BATCH   8
#define SEQ     512
#define DIM     512
#define NHEADS  8
#define DHEAD   64
#define MEMN    4096
#define TOPK    32
#define FFDIM   2048
#define DEPTH   6
#define MROWS   (BATCH*SEQ)    /* 4096 */
#define NBH     (BATCH*NHEADS) /* 64 */
#define ATT_SCALE 0.125f
#define PQ      (DIM*DIM/2)
#define PF      (DIM*FFDIM/2)

// ---------------- scratch (device globals; no allocation allowed) ----------
__device__ float g_X [MROWS*DIM];
__device__ float g_H [MROWS*DIM];
__device__ float g_Q [MROWS*DIM];
__device__ float g_K [MROWS*DIM];
__device__ float g_V [MROWS*DIM];
__device__ float g_AO[MROWS*DIM];
__device__ float g_FF[MROWS*FFDIM];
__device__ float g_S [(size_t)NBH*SEQ*MEMN];
__device__ float g_P [(size_t)NBH*SEQ*SEQ];
__device__ float g_TV[(size_t)NBH*SEQ*TOPK];
__device__ int   g_TI[(size_t)NBH*SEQ*TOPK];
#define WTOTAL (24*PQ + 12*PF)
__device__ unsigned g_WH[WTOTAL];
__device__ unsigned g_WL[WTOTAL];

__device__ __forceinline__ float warp_sum(float v) {
    #pragma unroll
    for (int o = 16; o > 0; o >>= 1) v += __shfl_xor_sync(0xffffffffu, v, o);
    return v;
}
__device__ __forceinline__ float warp_max(float v) {
    #pragma unroll
    for (int o = 16; o > 0; o >>= 1) v = fmaxf(v, __shfl_xor_sync(0xffffffffu, v, o));
    return v;
}
__device__ __forceinline__ float gelu_f(float v) {
    float c = v + 0.044715f * v * v * v;
    return 0.5f * v * (1.0f + tanhf(0.7978845608028654f * c));
}
__device__ __forceinline__ unsigned bfpack(float x, float y) {
    __nv_bfloat162 p = __floats2bfloat162_rn(x, y);
    return *reinterpret_cast<unsigned*>(&p);
}
__device__ __forceinline__ float bfhi(float x) {
    return __bfloat162float(__float2bfloat16(x));
}
__device__ __forceinline__ void mma_bf16(float& d0, float& d1, float& d2, float& d3,
                                         unsigned a0, unsigned a1, unsigned a2, unsigned a3,
                                         unsigned b0, unsigned b1) {
    asm volatile(
        "mma.sync.aligned.m16n8k16.row.col.f32.bf16.bf16.f32 "
        "{%0,%1,%2,%3}, {%4,%5,%6,%7}, {%8,%9}, {%0,%1,%2,%3};\n"
        : "+f"(d0), "+f"(d1), "+f"(d2), "+f"(d3)
        : "r"(a0), "r"(a1), "r"(a2), "r"(a3), "r"(b0), "r"(b1));
}

// ---- weight pre-split: W[K,N] fp32 -> packed (k,k+1) bf16 hi/lo words -----
__global__ void split_w(const float* __restrict__ W, unsigned* __restrict__ WH,
                        unsigned* __restrict__ WL, int KN2, int N) {
    int l = blockIdx.y;
    int idx = blockIdx.x * 256 + threadIdx.x;
    if (idx >= KN2) return;
    int kpr = idx / N, c = idx - kpr * N;
    const float* Wl = W + (size_t)l * 2 * KN2;
    float x = Wl[(size_t)(2*kpr) * N + c];
    float y = Wl[(size_t)(2*kpr+1) * N + c];
    float hx = bfhi(x), hy = bfhi(y);
    WH[(size_t)l*KN2 + idx] = bfpack(hx, hy);
    WL[(size_t)l*KN2 + idx] = bfpack(x - hx, y - hy);
}

// ---------------- LayerNorm -------------------------------------------------
__global__ void ln_kernel(const float* __restrict__ x,
                          const float* __restrict__ sc,
                          const float* __restrict__ bi,
                          float* __restrict__ out) {
    int row = blockIdx.x;
    int tid = threadIdx.x;
    const float4* xr = reinterpret_cast<const float4*>(x + (size_t)row * DIM);
    float4 v = xr[tid];
    float s  = v.x + v.y + v.z + v.w;
    float sq = v.x*v.x + v.y*v.y + v.z*v.z + v.w*v.w;
    __shared__ float ss[4], sqs[4];
    s  = warp_sum(s);
    sq = warp_sum(sq);
    int w = tid >> 5, lane = tid & 31;
    if (lane == 0) { ss[w] = s; sqs[w] = sq; }
    __syncthreads();
    float tot  = ss[0] + ss[1] + ss[2] + ss[3];
    float totq = sqs[0] + sqs[1] + sqs[2] + sqs[3];
    float mean = tot * (1.0f / DIM);
    float var  = totq * (1.0f / DIM) - mean * mean;
    float rstd = rsqrtf(var + 1e-5f);
    float4 sv = reinterpret_cast<const float4*>(sc)[tid];
    float4 bv = reinterpret_cast<const float4*>(bi)[tid];
    float4 o;
    o.x = (v.x - mean) * rstd * sv.x + bv.x;
    o.y = (v.y - mean) * rstd * sv.y + bv.y;
    o.z = (v.z - mean) * rstd * sv.z + bv.z;
    o.w = (v.w - mean) * rstd * sv.w + bv.w;
    reinterpret_cast<float4*>(out + (size_t)row * DIM)[tid] = o;
}

// ---- 128x128 CTA / 4 warps / 64x64 warp tiles; pipelined bf16-split GEMM --
#define SW  136
__device__ __forceinline__ void gemm_body(
    const float* __restrict__ A, const unsigned* __restrict__ BH,
    const unsigned* __restrict__ BL,
    const float* __restrict__ R, float* __restrict__ C,
    int N, int K, int act, int bx, int by)
{
    __shared__ unsigned AsH[2][8*SW], AsL[2][8*SW];
    __shared__ unsigned BsH[2][8*SW], BsL[2][8*SW];
    int tid = threadIdx.x, lane = tid & 31, warp = tid >> 5;
    int wm = warp & 1, wn = warp >> 1;        // 2x2 warp grid, 64x64 tiles
    int g = lane >> 2, tg = lane & 3;

    int kp = tid >> 4, col8 = (tid & 15) * 8; // B loader: 8 kpairs x 128 cols

    const float*    Ab  = A  + (size_t)(by * 128 + tid) * K;   // one row/thread
    const unsigned* BHb = BH + (size_t)kp * N + bx * 128 + col8;
    const unsigned* BLb = BL + (size_t)kp * N + bx * 128 + col8;

    float acc[4][8][4];
    #pragma unroll
    for (int mi = 0; mi < 4; mi++)
        #pragma unroll
        for (int ni = 0; ni < 8; ni++)
            #pragma unroll
            for (int r = 0; r < 4; r++) acc[mi][ni][r] = 0.f;

    float4 a0 = *reinterpret_cast<const float4*>(Ab);
    float4 a1 = *reinterpret_cast<const float4*>(Ab + 4);
    float4 a2 = *reinterpret_cast<const float4*>(Ab + 8);
    float4 a3 = *reinterpret_cast<const float4*>(Ab + 12);
    uint4  bh0 = *reinterpret_cast<const uint4*>(BHb);
    uint4  bh1 = *reinterpret_cast<const uint4*>(BHb + 4);
    uint4  bl0 = *reinterpret_cast<const uint4*>(BLb);
    uint4  bl1 = *reinterpret_cast<const uint4*>(BLb + 4);

    int buf = 0;
    for (int k0 = 0; k0 < K; k0 += 16) {
        // STS current stage
        {
            float xs[16] = {a0.x,a0.y,a0.z,a0.w, a1.x,a1.y,a1.z,a1.w,
                            a2.x,a2.y,a2.z,a2.w, a3.x,a3.y,a3.z,a3.w};
            #pragma unroll
            for (int j = 0; j < 8; j++) {
                float x = xs[2*j], y = xs[2*j+1];
                float hx = bfhi(x), hy = bfhi(y);
                AsH[buf][j*SW + tid] = bfpack(hx, hy);
                AsL[buf][j*SW + tid] = bfpack(x - hx, y - hy);
            }
            *reinterpret_cast<uint4*>(&BsH[buf][kp*SW + col8])     = bh0;
            *reinterpret_cast<uint4*>(&BsH[buf][kp*SW + col8 + 4]) = bh1;
            *reinterpret_cast<uint4*>(&BsL[buf][kp*SW + col8])     = bl0;
            *reinterpret_cast<uint4*>(&BsL[buf][kp*SW + col8 + 4]) = bl1;
        }
        __syncthreads();
        // prefetch next stage
        if (k0 + 16 < K) {
            a0 = *reinterpret_cast<const float4*>(Ab + k0 + 16);
            a1 = *reinterpret_cast<const float4*>(Ab + k0 + 20);
            a2 = *reinterpret_cast<const float4*>(Ab + k0 + 24);
            a3 = *reinterpret_cast<const float4*>(Ab + k0 + 28);
            const unsigned* bhn = BHb + (size_t)(k0/2 + 8) * N;
            const unsigned* bln = BLb + (size_t)(k0/2 + 8) * N;
            bh0 = *reinterpret_cast<const uint4*>(bhn);
            bh1 = *reinterpret_cast<const uint4*>(bhn + 4);
            bl0 = *reinterpret_cast<const uint4*>(bln);
            bl1 = *reinterpret_cast<const uint4*>(bln + 4);
        }
        // compute current stage
        const unsigned* asH = AsH[buf]; const unsigned* asL = AsL[buf];
        const unsigned* bsH = BsH[buf]; const unsigned* bsL = BsL[buf];
        unsigned afH[4][4], afL[4][4];
        #pragma unroll
        for (int mi = 0; mi < 4; mi++) {
            int rb = wm*64 + mi*16 + g;
            afH[mi][0] = asH[tg*SW + rb];       afL[mi][0] = asL[tg*SW + rb];
            afH[mi][1] = asH[tg*SW + rb+8];     afL[mi][1] = asL[tg*SW + rb+8];
            afH[mi][2] = asH[(tg+4)*SW + rb];   afL[mi][2] = asL[(tg+4)*SW + rb];
            afH[mi][3] = asH[(tg+4)*SW + rb+8]; afL[mi][3] = asL[(tg+4)*SW + rb+8];
        }
        #pragma unroll
        for (int ni = 0; ni < 8; ni++) {
            int cb = wn*64 + ni*8 + g;
            unsigned bH0 = bsH[tg*SW + cb], bH1 = bsH[(tg+4)*SW + cb];
            unsigned bL0 = bsL[tg*SW + cb], bL1 = bsL[(tg+4)*SW + cb];
            #pragma unroll
            for (int mi = 0; mi < 4; mi++) {
                mma_bf16(acc[mi][ni][0], acc[mi][ni][1], acc[mi][ni][2], acc[mi][ni][3],
                         afH[mi][0], afH[mi][1], afH[mi][2], afH[mi][3], bL0, bL1);
                mma_bf16(acc[mi][ni][0], acc[mi][ni][1], acc[mi][ni][2], acc[mi][ni][3],
                         afL[mi][0], afL[mi][1], afL[mi][2], afL[mi][3], bH0, bH1);
                mma_bf16(acc[mi][ni][0], acc[mi][ni][1], acc[mi][ni][2], acc[mi][ni][3],
                         afH[mi][0], afH[mi][1], afH[mi][2], afH[mi][3], bH0, bH1);
            }
        }
        buf ^= 1;
    }

    #pragma unroll
    for (int mi = 0; mi < 4; mi++) {
        #pragma unroll
        for (int ni = 0; ni < 8; ni++) {
            size_t row = (size_t)by*128 + wm*64 + mi*16 + g;
            size_t col = (size_t)bx*128 + wn*64 + ni*8 + tg*2;
            float v0 = acc[mi][ni][0], v1 = acc[mi][ni][1];
            float v2 = acc[mi][ni][2], v3 = acc[mi][ni][3];
            if (act) { v0 = gelu_f(v0); v1 = gelu_f(v1); v2 = gelu_f(v2); v3 = gelu_f(v3); }
            if (R) {
                float2 r0 = *reinterpret_cast<const float2*>(R + row*N + col);
                float2 r1 = *reinterpret_cast<const float2*>(R + (row+8)*N + col);
                v0 += r0.x; v1 += r0.y; v2 += r1.x; v3 += r1.y;
            }
            *reinterpret_cast<float2*>(C + row*N + col)     = make_float2(v0, v1);
            *reinterpret_cast<float2*>(C + (row+8)*N + col) = make_float2(v2, v3);
        }
    }
}

__global__ __launch_bounds__(128)
void gemm_tc(const float* __restrict__ A, const unsigned* __restrict__ BH,
             const unsigned* __restrict__ BL,
             const float* __restrict__ R, float* __restrict__ C,
             int N, int K, int act) {
    gemm_body(A, BH, BL, R, C, N, K, act, blockIdx.x, blockIdx.y);
}

__global__ __launch_bounds__(128)
void gemm_qkv(const float* __restrict__ H,
              const unsigned* __restrict__ WH, const unsigned* __restrict__ WL,
              int lofsQ, int lofsK, int lofsV,
              float* __restrict__ Q, float* __restrict__ K, float* __restrict__ V) {
    int ofs = (blockIdx.z == 0) ? lofsQ : (blockIdx.z == 1) ? lofsK : lofsV;
    float* C = (blockIdx.z == 0) ? Q : (blockIdx.z == 1) ? K : V;
    gemm_body(H, WH + ofs, WL + ofs, nullptr, C, DIM, DIM, 0, blockIdx.x, blockIdx.y);
}

// -------- bf16-split KNN sim (NT): S[bh,i,m] = scale * q . mk --------------
__global__ __launch_bounds__(256)
void knn_sim_tc(const float* __restrict__ Q, const float* __restrict__ MK,
                float* __restrict__ S) {
    __shared__ unsigned AsH[8*SW], AsL[8*SW];
    __shared__ unsigned BsH[8*SW], BsL[8*SW];
    int tid = threadIdx.x, lane = tid & 31, warp = tid >> 5;
    int wm = warp & 3, wn = warp >> 2;
    int g = lane >> 2, tg = lane & 3;
    int bh = blockIdx.z, b = bh >> 3, h = bh & 7;

    int lRow = tid >> 1, lJ0 = (tid & 1) * 4;
    const float* Qb = Q + (size_t)(b*SEQ + blockIdx.y*128 + lRow) * DIM + h*DHEAD + lJ0*2;
    const float* Mb = MK + (size_t)(b*MEMN + blockIdx.x*128 + lRow) * DHEAD + lJ0*2;

    float acc[2][8][4];
    #pragma unroll
    for (int mi = 0; mi < 2; mi++)
        #pragma unroll
        for (int ni = 0; ni < 8; ni++)
            #pragma unroll
            for (int r = 0; r < 4; r++) acc[mi][ni][r] = 0.f;

    for (int k0 = 0; k0 < DHEAD; k0 += 16) {
        float4 a0 = *reinterpret_cast<const float4*>(Qb + k0);
        float4 a1 = *reinterpret_cast<const float4*>(Qb + k0 + 4);
        float af8[8] = {a0.x,a0.y,a0.z,a0.w,a1.x,a1.y,a1.z,a1.w};
        float4 b0 = *reinterpret_cast<const float4*>(Mb + k0);
        float4 b1 = *reinterpret_cast<const float4*>(Mb + k0 + 4);
        float bf8[8] = {b0.x,b0.y,b0.z,b0.w,b1.x,b1.y,b1.z,b1.w};
        #pragma unroll
        for (int jj = 0; jj < 4; jj++) {
            float x = af8[2*jj], y = af8[2*jj+1];
            float hx = bfhi(x), hy = bfhi(y);
            AsH[(lJ0+jj)*SW + lRow] = bfpack(hx, hy);
            AsL[(lJ0+jj)*SW + lRow] = bfpack(x - hx, y - hy);
            float u = bf8[2*jj], v = bf8[2*jj+1];
            float hu = bfhi(u), hv = bfhi(v);
            BsH[(lJ0+jj)*SW + lRow] = bfpack(hu, hv);
            BsL[(lJ0+jj)*SW + lRow] = bfpack(u - hu, v - hv);
        }
        __syncthreads();
        unsigned afH[2][4], afL[2][4];
        #pragma unroll
        for (int mi = 0; mi < 2; mi++) {
            int rb = wm*32 + mi*16 + g;
            afH[mi][0] = AsH[tg*SW + rb];       afL[mi][0] = AsL[tg*SW + rb];
            afH[mi][1] = AsH[tg*SW + rb+8];     afL[mi][1] = AsL[tg*SW + rb+8];
            afH[mi][2] = AsH[(tg+4)*SW + rb];   afL[mi][2] = AsL[(tg+4)*SW + rb];
            afH[mi][3] = AsH[(tg+4)*SW + rb+8]; afL[mi][3] = AsL[(tg+4)*SW + rb+8];
        }
        #pragma unroll
        for (int ni = 0; ni < 8; ni++) {
            int cb = wn*64 + ni*8 + g;
            unsigned bH0 = BsH[tg*SW + cb], bH1 = BsH[(tg+4)*SW + cb];
            unsigned bL0 = BsL[tg*SW + cb], bL1 = BsL[(tg+4)*SW + cb];
            #pragma unroll
            for (int mi = 0; mi < 2; mi++) {
                mma_bf16(acc[mi][ni][0], acc[mi][ni][1], acc[mi][ni][2], acc[mi][ni][3],
                         afH[mi][0], afH[mi][1], afH[mi][2], afH[mi][3], bL0, bL1);
                mma_bf16(acc[mi][ni][0], acc[mi][ni][1], acc[mi][ni][2], acc[mi][ni][3],
                         afL[mi][0], afL[mi][1], afL[mi][2], afL[mi][3], bH0, bH1);
                mma_bf16(acc[mi][ni][0], acc[mi][ni][1], acc[mi][ni][2], acc[mi][ni][3],
                         afH[mi][0], afH[mi][1], afH[mi][2], afH[mi][3], bH0, bH1);
            }
        }
        __syncthreads();
    }

    #pragma unroll
    for (int mi = 0; mi < 2; mi++) {
        #pragma unroll
        for (int ni = 0; ni < 8; ni++) {
            size_t iG = (size_t)blockIdx.y*128 + wm*32 + mi*16 + g;
            size_t mG = (size_t)blockIdx.x*128 + wn*64 + ni*8 + tg*2;
            *reinterpret_cast<float2*>(S + ((size_t)bh*SEQ + iG)*MEMN + mG) =
                make_float2(acc[mi][ni][0]*ATT_SCALE, acc[mi][ni][1]*ATT_SCALE);
            *reinterpret_cast<float2*>(S + ((size_t)bh*SEQ + iG + 8)*MEMN + mG) =
                make_float2(acc[mi][ni][2]*ATT_SCALE, acc[mi][ni][3]*ATT_SCALE);
        }
    }
}

// -------- bf16-split local sim (NT): P[bh,i,j] = scale * q . k -------------
__global__ __launch_bounds__(256)
void sim_local_tc(const float* __restrict__ Q, const float* __restrict__ Km,
                  float* __restrict__ P) {
    if (blockIdx.x > blockIdx.y) return;
    __shared__ unsigned AsH[8*SW], AsL[8*SW];
    __shared__ unsigned BsH[8*SW], BsL[8*SW];
    int tid = threadIdx.x, lane = tid & 31, warp = tid >> 5;
    int wm = warp & 3, wn = warp >> 2;
    int g = lane >> 2, tg = lane & 3;
    int bh = blockIdx.z, b = bh >> 3, h = bh & 7;

    int lRow = tid >> 1, lJ0 = (tid & 1) * 4;
    const float* Qb = Q + (size_t)(b*SEQ + blockIdx.y*128 + lRow) * DIM + h*DHEAD + lJ0*2;
    const float* Mb = Km + (size_t)(b*SEQ + blockIdx.x*128 + lRow) * DIM + h*DHEAD + lJ0*2;

    float acc[2][8][4];
    #pragma unroll
    for (int mi = 0; mi < 2; mi++)
        #pragma unroll
        for (int ni = 0; ni < 8; ni++)
            #pragma unroll
            for (int r = 0; r < 4; r++) acc[mi][ni][r] = 0.f;

    for (int k0 = 0; k0 < DHEAD; k0 += 16) {
        float4 a0 = *reinterpret_cast<const float4*>(Qb + k0);
        float4 a1 = *reinterpret_cast<const float4*>(Qb + k0 + 4);
        float af8[8] = {a0.x,a0.y,a0.z,a0.w,a1.x,a1.y,a1.z,a1.w};
        float4 b0 = *reinterpret_cast<const float4*>(Mb + k0);
        float4 b1 = *reinterpret_cast<const float4*>(Mb + k0 + 4);
        float bf8[8] = {b0.x,b0.y,b0.z,b0.w,b1.x,b1.y,b1.z,b1.w};
        #pragma unroll
        for (int jj = 0; jj < 4; jj++) {
            float x = af8[2*jj], y = af8[2*jj+1];
            float hx = bfhi(x), hy = bfhi(y);
            AsH[(lJ0+jj)*SW + lRow] = bfpack(hx, hy);
            AsL[(lJ0+jj)*SW + lRow] = bfpack(x - hx, y - hy);
            float u = bf8[2*jj], v = bf8[2*jj+1];
            float hu = bfhi(u), hv = bfhi(v);
            BsH[(lJ0+jj)*SW + lRow] = bfpack(hu, hv);
            BsL[(lJ0+jj)*SW + lRow] = bfpack(u - hu, v - hv);
        }
        __syncthreads();
        unsigned afH[2][4], afL[2][4];
        #pragma unroll
        for (int mi = 0; mi < 2; mi++) {
            int rb = wm*32 + mi*16 + g;
            afH[mi][0] = AsH[tg*SW + rb];       afL[mi][0] = AsL[tg*SW + rb];
            afH[mi][1] = AsH[tg*SW + rb+8];     afL[mi][1] = AsL[tg*SW + rb+8];
            afH[mi][2] = AsH[(tg+4)*SW + rb];   afL[mi][2] = AsL[(tg+4)*SW + rb];
            afH[mi][3] = AsH[(tg+4)*SW + rb+8]; afL[mi][3] = AsL[(tg+4)*SW + rb+8];
        }
        #pragma unroll
        for (int ni = 0; ni < 8; ni++) {
            int cb = wn*64 + ni*8 + g;
            unsigned bH0 = BsH[tg*SW + cb], bH1 = BsH[(tg+4)*SW + cb];
            unsigned bL0 = BsL[tg*SW + cb], bL1 = BsL[(tg+4)*SW + cb];
            #pragma unroll
            for (int mi = 0; mi < 2; mi++) {
                mma_bf16(acc[mi][ni][0], acc[mi][ni][1], acc[mi][ni][2], acc[mi][ni][3],
                         afH[mi][0], afH[mi][1], afH[mi][2], afH[mi][3], bL0, bL1);
                mma_bf16(acc[mi][ni][0], acc[mi][ni][1], acc[mi][ni][2], acc[mi][ni][3],
                         afL[mi][0], afL[mi][1], afL[mi][2], afL[mi][3], bH0, bH1);
                mma_bf16(acc[mi][ni][0], acc[mi][ni][1], acc[mi][ni][2], acc[mi][ni][3],
                         afH[mi][0], afH[mi][1], afH[mi][2], afH[mi][3], bH0, bH1);
            }
        }
        __syncthreads();
    }

    #pragma unroll
    for (int mi = 0; mi < 2; mi++) {
        #pragma unroll
        for (int ni = 0; ni < 8; ni++) {
            size_t iG = (size_t)blockIdx.y*128 + wm*32 + mi*16 + g;
            size_t jG = (size_t)blockIdx.x*128 + wn*64 + ni*8 + tg*2;
            *reinterpret_cast<float2*>(P + ((size_t)bh*SEQ + iG)*SEQ + jG) =
                make_float2(acc[mi][ni][0]*ATT_SCALE, acc[mi][ni][1]*ATT_SCALE);
            *reinterpret_cast<float2*>(P + ((size_t)bh*SEQ + iG + 8)*SEQ + jG) =
                make_float2(acc[mi][ni][2]*ATT_SCALE, acc[mi][ni][3]*ATT_SCALE);
        }
    }
}

// -------- causal row softmax: one warp per row, shuffle-only ---------------
__global__ __launch_bounds__(256)
void softmax_causal(float* __restrict__ P) {
    int w = threadIdx.x >> 5, lane = threadIdx.x & 31;
    int i = blockIdx.x * 8 + w, bh = blockIdx.y;
    int n = i + 1;
    int fillEnd = ((i >> 7) + 1) << 7;
    float* row = P + ((size_t)bh*SEQ + i)*SEQ;
    float lm = -1e30f;
    for (int j = lane; j < n; j += 32) lm = fmaxf(lm, row[j]);
    lm = warp_max(lm);
    float ls = 0.f;
    for (int j = lane; j < n; j += 32) { float e = __expf(row[j] - lm); row[j] = e; ls += e; }
    ls = warp_sum(ls);
    float inv = 1.0f / ls;
    for (int j = lane; j < n; j += 32) row[j] *= inv;
    for (int j = n + lane; j < fillEnd; j += 32) row[j] = 0.f;
}

// -------- knn row softmax: one warp per row; TOPK=32 maps to lanes ---------
__global__ __launch_bounds__(256)
void softmax_knn(float* __restrict__ P, float* __restrict__ TV) {
    int w = threadIdx.x >> 5, lane = threadIdx.x & 31;
    int i = blockIdx.x * 8 + w, bh = blockIdx.y;
    int n = i + 1;
    int fillEnd = ((i >> 7) + 1) << 7;
    float* row = P + ((size_t)bh*SEQ + i)*SEQ;
    float* tvp = TV + ((size_t)bh*SEQ + i)*TOPK;
    float tvv = tvp[lane];
    float lm = tvv;
    for (int j = lane; j < n; j += 32) lm = fmaxf(lm, row[j]);
    lm = warp_max(lm);
    float te = __expf(tvv - lm);
    float ls = te;
    for (int j = lane; j < n; j += 32) { float e = __expf(row[j] - lm); row[j] = e; ls += e; }
    ls = warp_sum(ls);
    float inv = 1.0f / ls;
    for (int j = lane; j < n; j += 32) row[j] *= inv;
    for (int j = n + lane; j < fillEnd; j += 32) row[j] = 0.f;
    tvp[lane] = te * inv;
}

// -------- memory gather: 8 rows per 512-thread block -----------------------
__global__ __launch_bounds__(512)
void mem_gather(const float* __restrict__ MV, const float* __restrict__ TV,
                const int* __restrict__ TI, float* __restrict__ O) {
    int sub = threadIdx.x >> 6, d = threadIdx.x & 63;
    int i = blockIdx.x * 8 + sub;
    int bh = blockIdx.y, b = bh >> 3, h = bh & 7;
    __shared__ float tv[8][TOPK];
    __shared__ int   ti[8][TOPK];
    if (d < TOPK) {
        tv[sub][d] = TV[((size_t)bh*SEQ + i)*TOPK + d];
        ti[sub][d] = TI[((size_t)bh*SEQ + i)*TOPK + d];
    }
    __syncthreads();
    const float* mvb = MV + (size_t)b * MEMN * DHEAD;
    float acc = 0.f;
    #pragma unroll
    for (int t = 0; t < TOPK; t++)
        acc += tv[sub][t] * mvb[(size_t)ti[sub][t] * DHEAD + d];
    O[(size_t)(b*SEQ + i)*DIM + h*DHEAD + d] = acc;
}

// -------- AV GEMM: O(+)= P[bh] @ V[b,:,h,:]; 128x64 tile, causal-truncated -
#define SWB 72
__global__ __launch_bounds__(256)
void av_tc(const float* __restrict__ P, const float* __restrict__ Vm,
           float* __restrict__ O, int accum) {
    __shared__ unsigned AsH[8*SW], AsL[8*SW];
    __shared__ unsigned BsH[8*SWB], BsL[8*SWB];
    int tid = threadIdx.x, lane = tid & 31, warp = tid >> 5;
    int wm = warp & 3, wn = warp >> 2;
    int g = lane >> 2, tg = lane & 3;
    int by = blockIdx.x, bh = blockIdx.y, b = bh >> 3, h = bh & 7;
    int kmax = (by + 1) * 128;

    int aRow = tid >> 1, aJ0 = (tid & 1) * 4;
    int kp = tid >> 5, col2 = (tid & 31) * 2;

    const float* Ab = P + ((size_t)bh*SEQ + by*128 + aRow)*SEQ + aJ0*2;
    const float* Bb = Vm + (size_t)(b*SEQ + kp*2)*DIM + h*DHEAD + col2;

    float acc[2][4][4];
    #pragma unroll
    for (int mi = 0; mi < 2; mi++)
        #pragma unroll
        for (int ni = 0; ni < 4; ni++)
            #pragma unroll
            for (int r = 0; r < 4; r++) acc[mi][ni][r] = 0.f;

    for (int k0 = 0; k0 < kmax; k0 += 16) {
        float4 a0 = *reinterpret_cast<const float4*>(Ab + k0);
        float4 a1 = *reinterpret_cast<const float4*>(Ab + k0 + 4);
        float af8[8] = {a0.x,a0.y,a0.z,a0.w,a1.x,a1.y,a1.z,a1.w};
        #pragma unroll
        for (int jj = 0; jj < 4; jj++) {
            float x = af8[2*jj], y = af8[2*jj+1];
            float hx = bfhi(x), hy = bfhi(y);
            AsH[(aJ0+jj)*SW + aRow] = bfpack(hx, hy);
            AsL[(aJ0+jj)*SW + aRow] = bfpack(x - hx, y - hy);
        }
        float2 b0 = *reinterpret_cast<const float2*>(Bb + (size_t)k0*DIM);
        float2 b1 = *reinterpret_cast<const float2*>(Bb + (size_t)k0*DIM + DIM);
        {
            float hx = bfhi(b0.x), hy = bfhi(b1.x);
            BsH[kp*SWB + col2]   = bfpack(hx, hy);
            BsL[kp*SWB + col2]   = bfpack(b0.x - hx, b1.x - hy);
            float hx2 = bfhi(b0.y), hy2 = bfhi(b1.y);
            BsH[kp*SWB + col2+1] = bfpack(hx2, hy2);
            BsL[kp*SWB + col2+1] = bfpack(b0.y - hx2, b1.y - hy2);
        }
        __syncthreads();

        unsigned afH[2][4], afL[2][4];
        #pragma unroll
        for (int mi = 0; mi < 2; mi++) {
            int rb = wm*32 + mi*16 + g;
            afH[mi][0] = AsH[tg*SW + rb];       afL[mi][0] = AsL[tg*SW + rb];
            afH[mi][1] = AsH[tg*SW + rb+8];     afL[mi][1] = AsL[tg*SW + rb+8];
            afH[mi][2] = AsH[(tg+4)*SW + rb];   afL[mi][2] = AsL[(tg+4)*SW + rb];
            afH[mi][3] = AsH[(tg+4)*SW + rb+8]; afL[mi][3] = AsL[(tg+4)*SW + rb+8];
        }
        #pragma unroll
        for (int ni = 0; ni < 4; ni++) {
            int cb = wn*32 + ni*8 + g;
            unsigned bH0 = BsH[tg*SWB + cb], bH1 = BsH[(tg+4)*SWB + cb];
            unsigned bL0 = BsL[tg*SWB + cb], bL1 = BsL[(tg+4)*SWB + cb];
            #pragma unroll
            for (int mi = 0; mi < 2; mi++) {
                mma_bf16(acc[mi][ni][0], acc[mi][ni][1], acc[mi][ni][2], acc[mi][ni][3],
                         afH[mi][0], afH[mi][1], afH[mi][2], afH[mi][3], bL0, bL1);
                mma_bf16(acc[mi][ni][0], acc[mi][ni][1], acc[mi][ni][2], acc[mi][ni][3],
                         afL[mi][0], afL[mi][1], afL[mi][2], afL[mi][3], bH0, bH1);
                mma_bf16(acc[mi][ni][0], acc[mi][ni][1], acc[mi][ni][2], acc[mi][ni][3],
                         afH[mi][0], afH[mi][1], afH[mi][2], afH[mi][3], bH0, bH1);
            }
        }
        __syncthreads();
    }

    #pragma unroll
    for (int mi = 0; mi < 2; mi++) {
        #pragma unroll
        for (int ni = 0; ni < 4; ni++) {
            int row = by*128 + wm*32 + mi*16 + g;
            int col = wn*32 + ni*8 + tg*2;
            float* o0 = O + (size_t)(b*SEQ + row)*DIM + h*DHEAD + col;
            float* o1 = O + (size_t)(b*SEQ + row + 8)*DIM + h*DHEAD + col;
            float v0 = acc[mi][ni][0], v1 = acc[mi][ni][1];
            float v2 = acc[mi][ni][2], v3 = acc[mi][ni][3];
            if (accum) {
                float2 r0 = *reinterpret_cast<const float2*>(o0);
                float2 r1 = *reinterpret_cast<const float2*>(o1);
                v0 += r0.x; v1 += r0.y; v2 += r1.x; v3 += r1.y;
            }
            *reinterpret_cast<float2*>(o0) = make_float2(v0, v1);
            *reinterpret_cast<float2*>(o1) = make_float2(v2, v3);
        }
    }
}

// -------- top-32 per (bh,i): smem iterative argmax --------------------------
__global__ __launch_bounds__(256)
void topk_kernel(const float* __restrict__ S, float* __restrict__ TV,
                 int* __restrict__ TI) {
    int i = blockIdx.x, bh = blockIdx.y;
    const float* row = S + ((size_t)bh*SEQ + i)*MEMN;
    __shared__ float sv[MEMN];
    __shared__ float wv[8];
    __shared__ int   wi[8];
    __shared__ int wini;
    int tid = threadIdx.x;

    float lmax = -1e30f; int lidx = 0;
    #pragma unroll 4
    for (int j = 0; j < 16; j++) {
        int m = tid + 256*j;
        float v = row[m];
        sv[m] = v;
        if (v > lmax) { lmax = v; lidx = m; }
    }
    for (int t = 0; t < TOPK; t++) {
        float v = lmax; int idx = lidx;
        #pragma unroll
        for (int o = 16; o > 0; o >>= 1) {
            float ov = __shfl_xor_sync(0xffffffffu, v, o);
            int   oi = __shfl_xor_sync(0xffffffffu, idx, o);
            if (ov > v) { v = ov; idx = oi; }
        }
        if ((tid & 31) == 0) { wv[tid>>5] = v; wi[tid>>5] = idx; }
        __syncthreads();
        if (tid < 32) {
            float v2 = (tid < 8) ? wv[tid] : -1e30f;
            int   i2 = (tid < 8) ? wi[tid] : 0;
            #pragma unroll
            for (int o = 4; o > 0; o >>= 1) {
                float ov = __shfl_xor_sync(0xffffffffu, v2, o);
                int   oi = __shfl_xor_sync(0xffffffffu, i2, o);
                if (ov > v2) { v2 = ov; i2 = oi; }
            }
            if (tid == 0) {
                wini = i2;
                TV[((size_t)bh*SEQ + i)*TOPK + t] = v2;
                TI[((size_t)bh*SEQ + i)*TOPK + t] = i2;
            }
        }
        __syncthreads();
        int widx = wini;
        if ((widx & 255) == tid) {
            sv[widx] = -1e30f;
            lmax = -1e30f; lidx = 0;
            #pragma unroll 4
            for (int j = 0; j < 16; j++) {
                int m = tid + 256*j;
                float vv = sv[m];
                if (vv > lmax) { lmax = vv; lidx = m; }
            }
        }
    }
}

// ---------------- host orchestration --------------------------------------
extern "C" void kernel_launch(void* const* d_in, const int* in_sizes, int n_in,
                              void* d_out, int out_size) {
    const float* x     = (const float*)d_in[0];
    const float* Wq    = (const float*)d_in[1];
    const float* Wk    = (const float*)d_in[2];
    const float* Wv    = (const float*)d_in[3];
    const float* Wo    = (const float*)d_in[4];
    const float* ln1s  = (const float*)d_in[5];
    const float* ln1b  = (const float*)d_in[6];
    const float* ln2s  = (const float*)d_in[7];
    const float* ln2b  = (const float*)d_in[8];
    const float* W1    = (const float*)d_in[9];
    const float* W2    = (const float*)d_in[10];
    const float* lnfs  = (const float*)d_in[11];
    const float* lnfb  = (const float*)d_in[12];
    const float* mem_k = (const float*)d_in[13];
    const float* mem_v = (const float*)d_in[14];

    float *X, *H, *Q, *K, *V, *AO, *FFb, *S, *P, *TV;
    int *TI; unsigned *WH, *WL;
    cudaGetSymbolAddress((void**)&X,  g_X);
    cudaGetSymbolAddress((void**)&H,  g_H);
    cudaGetSymbolAddress((void**)&Q,  g_Q);
    cudaGetSymbolAddress((void**)&K,  g_K);
    cudaGetSymbolAddress((void**)&V,  g_V);
    cudaGetSymbolAddress((void**)&AO, g_AO);
    cudaGetSymbolAddress((void**)&FFb, g_FF);
    cudaGetSymbolAddress((void**)&S,  g_S);
    cudaGetSymbolAddress((void**)&P,  g_P);
    cudaGetSymbolAddress((void**)&TV, g_TV);
    cudaGetSymbolAddress((void**)&TI, g_TI);
    cudaGetSymbolAddress((void**)&WH, g_WH);
    cudaGetSymbolAddress((void**)&WL, g_WL);

    cudaMemcpyAsync(X, x, sizeof(float) * MROWS * DIM, cudaMemcpyDeviceToDevice);

    const int OQ = 0, OK = 6*PQ, OV = 12*PQ, OO = 18*PQ, O1 = 24*PQ, O2 = 24*PQ + 6*PF;
    split_w<<<dim3(PQ/256, DEPTH), 256>>>(Wq, WH + OQ, WL + OQ, PQ, DIM);
    split_w<<<dim3(PQ/256, DEPTH), 256>>>(Wk, WH + OK, WL + OK, PQ, DIM);
    split_w<<<dim3(PQ/256, DEPTH), 256>>>(Wv, WH + OV, WL + OV, PQ, DIM);
    split_w<<<dim3(PQ/256, DEPTH), 256>>>(Wo, WH + OO, WL + OO, PQ, DIM);
    split_w<<<dim3(PF/256, DEPTH), 256>>>(W1, WH + O1, WL + O1, PF, FFDIM);
    split_w<<<dim3(PF/256, DEPTH), 256>>>(W2, WH + O2, WL + O2, PF, DIM);

    dim3 gD(DIM/128, MROWS/128);          // 4 x 32
    dim3 gQKV(DIM/128, MROWS/128, 3);
    dim3 gF(FFDIM/128, MROWS/128);        // 16 x 32
    dim3 gSim(MEMN/128, SEQ/128, NBH);
    dim3 gLoc(SEQ/128, SEQ/128, NBH);
    dim3 gRow(SEQ, NBH);
    dim3 gSm(SEQ/8, NBH);                 // warp-per-row softmax
    dim3 gGa(SEQ/8, NBH);                 // 8 rows per gather block
    dim3 gAV(MROWS/128 / BATCH, NBH);

    int mi = 0;
    for (int l = 0; l < DEPTH; l++) {
        ln_kernel<<<MROWS, 128>>>(X, ln1s + l*DIM, ln1b + l*DIM, H);
        gemm_qkv<<<gQKV, 128>>>(H, WH, WL, OQ + l*PQ, OK + l*PQ, OV + l*PQ, Q, K, V);
        if (l == 3 || l == 4) {
            const float* MK = mem_k + (size_t)mi * BATCH * MEMN * DHEAD;
            const float* MV = mem_v + (size_t)mi * BATCH * MEMN * DHEAD;
            knn_sim_tc<<<gSim, 256>>>(Q, MK, S);
            topk_kernel<<<gRow, 256>>>(S, TV, TI);
            sim_local_tc<<<gLoc, 256>>>(Q, K, P);
            softmax_knn<<<gSm, 256>>>(P, TV);
            mem_gather<<<gGa, 512>>>(MV, TV, TI, AO);
            av_tc<<<gAV, 256>>>(P, V, AO, 1);
            mi++;
        } else {
            sim_local_tc<<<gLoc, 256>>>(Q, K, P);
            softmax_causal<<<gSm, 256>>>(P);
            av_tc<<<gAV, 256>>>(P, V, AO, 0);
        }
        gemm_tc<<<gD, 128>>>(AO, WH + OO + l*PQ, WL + OO + l*PQ, X, X, DIM, DIM, 0);
        ln_kernel<<<MROWS, 128>>>(X, ln2s + l*DIM, ln2b + l*DIM, H);
        gemm_tc<<<gF, 128>>>(H, WH + O1 + l*PF, WL + O1 + l*PF, nullptr, FFb, FFDIM, DIM, 1);
        gemm_tc<<<gD, 128>>>(FFb, WH + O2 + l*PF, WL + O2 + l*PF, X, X, DIM, FFDIM, 0);
    }
    ln_kernel<<<MROWS, 128>>>(X, lnfs, lnfb, (float*)d_out);
}

// round 14
// speedup vs baseline: 1.5061x; 1.5061x over previous
#include <cuda_runtime.h>
#include <cuda_bf16.h>
#include <math.h>

#define BATCH   8
#define SEQ     512
#define DIM     512
#define NHEADS  8
#define DHEAD   64
#define MEMN    4096
#define TOPK    32
#define FFDIM   2048
#define DEPTH   6
#define MROWS   (BATCH*SEQ)    /* 4096 */
#define NBH     (BATCH*NHEADS) /* 64 */
#define ATT_SCALE 0.125f
#define PQ      (DIM*DIM/2)
#define PF      (DIM*FFDIM/2)

// ---------------- scratch (device globals; no allocation allowed) ----------
__device__ float g_X [MROWS*DIM];
__device__ float g_H [MROWS*DIM];
__device__ float g_Q [MROWS*DIM];
__device__ float g_K [MROWS*DIM];
__device__ float g_V [MROWS*DIM];
__device__ float g_AO[MROWS*DIM];
__device__ float g_FF[MROWS*FFDIM];
__device__ float g_S [(size_t)NBH*SEQ*MEMN];
__device__ float g_P [(size_t)NBH*SEQ*SEQ];
__device__ float g_TV[(size_t)NBH*SEQ*TOPK];
__device__ int   g_TI[(size_t)NBH*SEQ*TOPK];
#define WTOTAL (24*PQ + 12*PF)
__device__ unsigned g_WH[WTOTAL];
__device__ unsigned g_WL[WTOTAL];

__device__ __forceinline__ float warp_sum(float v) {
    #pragma unroll
    for (int o = 16; o > 0; o >>= 1) v += __shfl_xor_sync(0xffffffffu, v, o);
    return v;
}
__device__ __forceinline__ float warp_max(float v) {
    #pragma unroll
    for (int o = 16; o > 0; o >>= 1) v = fmaxf(v, __shfl_xor_sync(0xffffffffu, v, o));
    return v;
}
__device__ __forceinline__ float gelu_f(float v) {
    float c = v + 0.044715f * v * v * v;
    return 0.5f * v * (1.0f + tanhf(0.7978845608028654f * c));
}
__device__ __forceinline__ unsigned bfpack(float x, float y) {
    __nv_bfloat162 p = __floats2bfloat162_rn(x, y);
    return *reinterpret_cast<unsigned*>(&p);
}
__device__ __forceinline__ float bfhi(float x) {
    return __bfloat162float(__float2bfloat16(x));
}
__device__ __forceinline__ void mma_bf16(float& d0, float& d1, float& d2, float& d3,
                                         unsigned a0, unsigned a1, unsigned a2, unsigned a3,
                                         unsigned b0, unsigned b1) {
    asm volatile(
        "mma.sync.aligned.m16n8k16.row.col.f32.bf16.bf16.f32 "
        "{%0,%1,%2,%3}, {%4,%5,%6,%7}, {%8,%9}, {%0,%1,%2,%3};\n"
        : "+f"(d0), "+f"(d1), "+f"(d2), "+f"(d3)
        : "r"(a0), "r"(a1), "r"(a2), "r"(a3), "r"(b0), "r"(b1));
}

// ---- weight pre-split: W[K,N] fp32 -> packed (k,k+1) bf16 hi/lo words -----
__global__ void split_w(const float* __restrict__ W, unsigned* __restrict__ WH,
                        unsigned* __restrict__ WL, int KN2, int N) {
    int l = blockIdx.y;
    int idx = blockIdx.x * 256 + threadIdx.x;
    if (idx >= KN2) return;
    int kpr = idx / N, c = idx - kpr * N;
    const float* Wl = W + (size_t)l * 2 * KN2;
    float x = Wl[(size_t)(2*kpr) * N + c];
    float y = Wl[(size_t)(2*kpr+1) * N + c];
    float hx = bfhi(x), hy = bfhi(y);
    WH[(size_t)l*KN2 + idx] = bfpack(hx, hy);
    WL[(size_t)l*KN2 + idx] = bfpack(x - hx, y - hy);
}

// ---------------- LayerNorm -------------------------------------------------
__global__ void ln_kernel(const float* __restrict__ x,
                          const float* __restrict__ sc,
                          const float* __restrict__ bi,
                          float* __restrict__ out) {
    int row = blockIdx.x;
    int tid = threadIdx.x;
    const float4* xr = reinterpret_cast<const float4*>(x + (size_t)row * DIM);
    float4 v = xr[tid];
    float s  = v.x + v.y + v.z + v.w;
    float sq = v.x*v.x + v.y*v.y + v.z*v.z + v.w*v.w;
    __shared__ float ss[4], sqs[4];
    s  = warp_sum(s);
    sq = warp_sum(sq);
    int w = tid >> 5, lane = tid & 31;
    if (lane == 0) { ss[w] = s; sqs[w] = sq; }
    __syncthreads();
    float tot  = ss[0] + ss[1] + ss[2] + ss[3];
    float totq = sqs[0] + sqs[1] + sqs[2] + sqs[3];
    float mean = tot * (1.0f / DIM);
    float var  = totq * (1.0f / DIM) - mean * mean;
    float rstd = rsqrtf(var + 1e-5f);
    float4 sv = reinterpret_cast<const float4*>(sc)[tid];
    float4 bv = reinterpret_cast<const float4*>(bi)[tid];
    float4 o;
    o.x = (v.x - mean) * rstd * sv.x + bv.x;
    o.y = (v.y - mean) * rstd * sv.y + bv.y;
    o.z = (v.z - mean) * rstd * sv.z + bv.z;
    o.w = (v.w - mean) * rstd * sv.w + bv.w;
    reinterpret_cast<float4*>(out + (size_t)row * DIM)[tid] = o;
}

// ---- 128x128 CTA / 4 warps / 64x64 warp tiles; pipelined bf16-split GEMM --
#define SW  136
__device__ __forceinline__ void gemm_body(
    const float* __restrict__ A, const unsigned* __restrict__ BH,
    const unsigned* __restrict__ BL,
    const float* __restrict__ R, float* __restrict__ C,
    int N, int K, int act, int bx, int by)
{
    __shared__ unsigned AsH[2][8*SW], AsL[2][8*SW];
    __shared__ unsigned BsH[2][8*SW], BsL[2][8*SW];
    int tid = threadIdx.x, lane = tid & 31, warp = tid >> 5;
    int wm = warp & 1, wn = warp >> 1;        // 2x2 warp grid, 64x64 tiles
    int g = lane >> 2, tg = lane & 3;

    int kp = tid >> 4, col8 = (tid & 15) * 8; // B loader: 8 kpairs x 128 cols

    const float*    Ab  = A  + (size_t)(by * 128 + tid) * K;   // one row/thread
    const unsigned* BHb = BH + (size_t)kp * N + bx * 128 + col8;
    const unsigned* BLb = BL + (size_t)kp * N + bx * 128 + col8;

    float acc[4][8][4];
    #pragma unroll
    for (int mi = 0; mi < 4; mi++)
        #pragma unroll
        for (int ni = 0; ni < 8; ni++)
            #pragma unroll
            for (int r = 0; r < 4; r++) acc[mi][ni][r] = 0.f;

    float4 a0 = *reinterpret_cast<const float4*>(Ab);
    float4 a1 = *reinterpret_cast<const float4*>(Ab + 4);
    float4 a2 = *reinterpret_cast<const float4*>(Ab + 8);
    float4 a3 = *reinterpret_cast<const float4*>(Ab + 12);
    uint4  bh0 = *reinterpret_cast<const uint4*>(BHb);
    uint4  bh1 = *reinterpret_cast<const uint4*>(BHb + 4);
    uint4  bl0 = *reinterpret_cast<const uint4*>(BLb);
    uint4  bl1 = *reinterpret_cast<const uint4*>(BLb + 4);

    int buf = 0;
    for (int k0 = 0; k0 < K; k0 += 16) {
        // STS current stage
        {
            float xs[16] = {a0.x,a0.y,a0.z,a0.w, a1.x,a1.y,a1.z,a1.w,
                            a2.x,a2.y,a2.z,a2.w, a3.x,a3.y,a3.z,a3.w};
            #pragma unroll
            for (int j = 0; j < 8; j++) {
                float x = xs[2*j], y = xs[2*j+1];
                float hx = bfhi(x), hy = bfhi(y);
                AsH[buf][j*SW + tid] = bfpack(hx, hy);
                AsL[buf][j*SW + tid] = bfpack(x - hx, y - hy);
            }
            *reinterpret_cast<uint4*>(&BsH[buf][kp*SW + col8])     = bh0;
            *reinterpret_cast<uint4*>(&BsH[buf][kp*SW + col8 + 4]) = bh1;
            *reinterpret_cast<uint4*>(&BsL[buf][kp*SW + col8])     = bl0;
            *reinterpret_cast<uint4*>(&BsL[buf][kp*SW + col8 + 4]) = bl1;
        }
        __syncthreads();
        // prefetch next stage
        if (k0 + 16 < K) {
            a0 = *reinterpret_cast<const float4*>(Ab + k0 + 16);
            a1 = *reinterpret_cast<const float4*>(Ab + k0 + 20);
            a2 = *reinterpret_cast<const float4*>(Ab + k0 + 24);
            a3 = *reinterpret_cast<const float4*>(Ab + k0 + 28);
            const unsigned* bhn = BHb + (size_t)(k0/2 + 8) * N;
            const unsigned* bln = BLb + (size_t)(k0/2 + 8) * N;
            bh0 = *reinterpret_cast<const uint4*>(bhn);
            bh1 = *reinterpret_cast<const uint4*>(bhn + 4);
            bl0 = *reinterpret_cast<const uint4*>(bln);
            bl1 = *reinterpret_cast<const uint4*>(bln + 4);
        }
        // compute current stage
        const unsigned* asH = AsH[buf]; const unsigned* asL = AsL[buf];
        const unsigned* bsH = BsH[buf]; const unsigned* bsL = BsL[buf];
        unsigned afH[4][4], afL[4][4];
        #pragma unroll
        for (int mi = 0; mi < 4; mi++) {
            int rb = wm*64 + mi*16 + g;
            afH[mi][0] = asH[tg*SW + rb];       afL[mi][0] = asL[tg*SW + rb];
            afH[mi][1] = asH[tg*SW + rb+8];     afL[mi][1] = asL[tg*SW + rb+8];
            afH[mi][2] = asH[(tg+4)*SW + rb];   afL[mi][2] = asL[(tg+4)*SW + rb];
            afH[mi][3] = asH[(tg+4)*SW + rb+8]; afL[mi][3] = asL[(tg+4)*SW + rb+8];
        }
        #pragma unroll
        for (int ni = 0; ni < 8; ni++) {
            int cb = wn*64 + ni*8 + g;
            unsigned bH0 = bsH[tg*SW + cb], bH1 = bsH[(tg+4)*SW + cb];
            unsigned bL0 = bsL[tg*SW + cb], bL1 = bsL[(tg+4)*SW + cb];
            #pragma unroll
            for (int mi = 0; mi < 4; mi++) {
                mma_bf16(acc[mi][ni][0], acc[mi][ni][1], acc[mi][ni][2], acc[mi][ni][3],
                         afH[mi][0], afH[mi][1], afH[mi][2], afH[mi][3], bL0, bL1);
                mma_bf16(acc[mi][ni][0], acc[mi][ni][1], acc[mi][ni][2], acc[mi][ni][3],
                         afL[mi][0], afL[mi][1], afL[mi][2], afL[mi][3], bH0, bH1);
                mma_bf16(acc[mi][ni][0], acc[mi][ni][1], acc[mi][ni][2], acc[mi][ni][3],
                         afH[mi][0], afH[mi][1], afH[mi][2], afH[mi][3], bH0, bH1);
            }
        }
        buf ^= 1;
    }

    #pragma unroll
    for (int mi = 0; mi < 4; mi++) {
        #pragma unroll
        for (int ni = 0; ni < 8; ni++) {
            size_t row = (size_t)by*128 + wm*64 + mi*16 + g;
            size_t col = (size_t)bx*128 + wn*64 + ni*8 + tg*2;
            float v0 = acc[mi][ni][0], v1 = acc[mi][ni][1];
            float v2 = acc[mi][ni][2], v3 = acc[mi][ni][3];
            if (act) { v0 = gelu_f(v0); v1 = gelu_f(v1); v2 = gelu_f(v2); v3 = gelu_f(v3); }
            if (R) {
                float2 r0 = *reinterpret_cast<const float2*>(R + row*N + col);
                float2 r1 = *reinterpret_cast<const float2*>(R + (row+8)*N + col);
                v0 += r0.x; v1 += r0.y; v2 += r1.x; v3 += r1.y;
            }
            *reinterpret_cast<float2*>(C + row*N + col)     = make_float2(v0, v1);
            *reinterpret_cast<float2*>(C + (row+8)*N + col) = make_float2(v2, v3);
        }
    }
}

__global__ __launch_bounds__(128)
void gemm_tc(const float* __restrict__ A, const unsigned* __restrict__ BH,
             const unsigned* __restrict__ BL,
             const float* __restrict__ R, float* __restrict__ C,
             int N, int K, int act) {
    gemm_body(A, BH, BL, R, C, N, K, act, blockIdx.x, blockIdx.y);
}

__global__ __launch_bounds__(128)
void gemm_qkv(const float* __restrict__ H,
              const unsigned* __restrict__ WH, const unsigned* __restrict__ WL,
              int lofsQ, int lofsK, int lofsV,
              float* __restrict__ Q, float* __restrict__ K, float* __restrict__ V) {
    int ofs = (blockIdx.z == 0) ? lofsQ : (blockIdx.z == 1) ? lofsK : lofsV;
    float* C = (blockIdx.z == 0) ? Q : (blockIdx.z == 1) ? K : V;
    gemm_body(H, WH + ofs, WL + ofs, nullptr, C, DIM, DIM, 0, blockIdx.x, blockIdx.y);
}

// -------- bf16-split KNN sim (NT): S[bh,i,m] = scale * q . mk --------------
__global__ __launch_bounds__(256)
void knn_sim_tc(const float* __restrict__ Q, const float* __restrict__ MK,
                float* __restrict__ S) {
    __shared__ unsigned AsH[8*SW], AsL[8*SW];
    __shared__ unsigned BsH[8*SW], BsL[8*SW];
    int tid = threadIdx.x, lane = tid & 31, warp = tid >> 5;
    int wm = warp & 3, wn = warp >> 2;
    int g = lane >> 2, tg = lane & 3;
    int bh = blockIdx.z, b = bh >> 3, h = bh & 7;

    int lRow = tid >> 1, lJ0 = (tid & 1) * 4;
    const float* Qb = Q + (size_t)(b*SEQ + blockIdx.y*128 + lRow) * DIM + h*DHEAD + lJ0*2;
    const float* Mb = MK + (size_t)(b*MEMN + blockIdx.x*128 + lRow) * DHEAD + lJ0*2;

    float acc[2][8][4];
    #pragma unroll
    for (int mi = 0; mi < 2; mi++)
        #pragma unroll
        for (int ni = 0; ni < 8; ni++)
            #pragma unroll
            for (int r = 0; r < 4; r++) acc[mi][ni][r] = 0.f;

    for (int k0 = 0; k0 < DHEAD; k0 += 16) {
        float4 a0 = *reinterpret_cast<const float4*>(Qb + k0);
        float4 a1 = *reinterpret_cast<const float4*>(Qb + k0 + 4);
        float af8[8] = {a0.x,a0.y,a0.z,a0.w,a1.x,a1.y,a1.z,a1.w};
        float4 b0 = *reinterpret_cast<const float4*>(Mb + k0);
        float4 b1 = *reinterpret_cast<const float4*>(Mb + k0 + 4);
        float bf8[8] = {b0.x,b0.y,b0.z,b0.w,b1.x,b1.y,b1.z,b1.w};
        #pragma unroll
        for (int jj = 0; jj < 4; jj++) {
            float x = af8[2*jj], y = af8[2*jj+1];
            float hx = bfhi(x), hy = bfhi(y);
            AsH[(lJ0+jj)*SW + lRow] = bfpack(hx, hy);
            AsL[(lJ0+jj)*SW + lRow] = bfpack(x - hx, y - hy);
            float u = bf8[2*jj], v = bf8[2*jj+1];
            float hu = bfhi(u), hv = bfhi(v);
            BsH[(lJ0+jj)*SW + lRow] = bfpack(hu, hv);
            BsL[(lJ0+jj)*SW + lRow] = bfpack(u - hu, v - hv);
        }
        __syncthreads();
        unsigned afH[2][4], afL[2][4];
        #pragma unroll
        for (int mi = 0; mi < 2; mi++) {
            int rb = wm*32 + mi*16 + g;
            afH[mi][0] = AsH[tg*SW + rb];       afL[mi][0] = AsL[tg*SW + rb];
            afH[mi][1] = AsH[tg*SW + rb+8];     afL[mi][1] = AsL[tg*SW + rb+8];
            afH[mi][2] = AsH[(tg+4)*SW + rb];   afL[mi][2] = AsL[(tg+4)*SW + rb];
            afH[mi][3] = AsH[(tg+4)*SW + rb+8]; afL[mi][3] = AsL[(tg+4)*SW + rb+8];
        }
        #pragma unroll
        for (int ni = 0; ni < 8; ni++) {
            int cb = wn*64 + ni*8 + g;
            unsigned bH0 = BsH[tg*SW + cb], bH1 = BsH[(tg+4)*SW + cb];
            unsigned bL0 = BsL[tg*SW + cb], bL1 = BsL[(tg+4)*SW + cb];
            #pragma unroll
            for (int mi = 0; mi < 2; mi++) {
                mma_bf16(acc[mi][ni][0], acc[mi][ni][1], acc[mi][ni][2], acc[mi][ni][3],
                         afH[mi][0], afH[mi][1], afH[mi][2], afH[mi][3], bL0, bL1);
                mma_bf16(acc[mi][ni][0], acc[mi][ni][1], acc[mi][ni][2], acc[mi][ni][3],
                         afL[mi][0], afL[mi][1], afL[mi][2], afL[mi][3], bH0, bH1);
                mma_bf16(acc[mi][ni][0], acc[mi][ni][1], acc[mi][ni][2], acc[mi][ni][3],
                         afH[mi][0], afH[mi][1], afH[mi][2], afH[mi][3], bH0, bH1);
            }
        }
        __syncthreads();
    }

    #pragma unroll
    for (int mi = 0; mi < 2; mi++) {
        #pragma unroll
        for (int ni = 0; ni < 8; ni++) {
            size_t iG = (size_t)blockIdx.y*128 + wm*32 + mi*16 + g;
            size_t mG = (size_t)blockIdx.x*128 + wn*64 + ni*8 + tg*2;
            *reinterpret_cast<float2*>(S + ((size_t)bh*SEQ + iG)*MEMN + mG) =
                make_float2(acc[mi][ni][0]*ATT_SCALE, acc[mi][ni][1]*ATT_SCALE);
            *reinterpret_cast<float2*>(S + ((size_t)bh*SEQ + iG + 8)*MEMN + mG) =
                make_float2(acc[mi][ni][2]*ATT_SCALE, acc[mi][ni][3]*ATT_SCALE);
        }
    }
}

// -------- bf16-split local sim (NT): P[bh,i,j] = scale * q . k -------------
__global__ __launch_bounds__(256)
void sim_local_tc(const float* __restrict__ Q, const float* __restrict__ Km,
                  float* __restrict__ P) {
    if (blockIdx.x > blockIdx.y) return;
    __shared__ unsigned AsH[8*SW], AsL[8*SW];
    __shared__ unsigned BsH[8*SW], BsL[8*SW];
    int tid = threadIdx.x, lane = tid & 31, warp = tid >> 5;
    int wm = warp & 3, wn = warp >> 2;
    int g = lane >> 2, tg = lane & 3;
    int bh = blockIdx.z, b = bh >> 3, h = bh & 7;

    int lRow = tid >> 1, lJ0 = (tid & 1) * 4;
    const float* Qb = Q + (size_t)(b*SEQ + blockIdx.y*128 + lRow) * DIM + h*DHEAD + lJ0*2;
    const float* Mb = Km + (size_t)(b*SEQ + blockIdx.x*128 + lRow) * DIM + h*DHEAD + lJ0*2;

    float acc[2][8][4];
    #pragma unroll
    for (int mi = 0; mi < 2; mi++)
        #pragma unroll
        for (int ni = 0; ni < 8; ni++)
            #pragma unroll
            for (int r = 0; r < 4; r++) acc[mi][ni][r] = 0.f;

    for (int k0 = 0; k0 < DHEAD; k0 += 16) {
        float4 a0 = *reinterpret_cast<const float4*>(Qb + k0);
        float4 a1 = *reinterpret_cast<const float4*>(Qb + k0 + 4);
        float af8[8] = {a0.x,a0.y,a0.z,a0.w,a1.x,a1.y,a1.z,a1.w};
        float4 b0 = *reinterpret_cast<const float4*>(Mb + k0);
        float4 b1 = *reinterpret_cast<const float4*>(Mb + k0 + 4);
        float bf8[8] = {b0.x,b0.y,b0.z,b0.w,b1.x,b1.y,b1.z,b1.w};
        #pragma unroll
        for (int jj = 0; jj < 4; jj++) {
            float x = af8[2*jj], y = af8[2*jj+1];
            float hx = bfhi(x), hy = bfhi(y);
            AsH[(lJ0+jj)*SW + lRow] = bfpack(hx, hy);
            AsL[(lJ0+jj)*SW + lRow] = bfpack(x - hx, y - hy);
            float u = bf8[2*jj], v = bf8[2*jj+1];
            float hu = bfhi(u), hv = bfhi(v);
            BsH[(lJ0+jj)*SW + lRow] = bfpack(hu, hv);
            BsL[(lJ0+jj)*SW + lRow] = bfpack(u - hu, v - hv);
        }
        __syncthreads();
        unsigned afH[2][4], afL[2][4];
        #pragma unroll
        for (int mi = 0; mi < 2; mi++) {
            int rb = wm*32 + mi*16 + g;
            afH[mi][0] = AsH[tg*SW + rb];       afL[mi][0] = AsL[tg*SW + rb];
            afH[mi][1] = AsH[tg*SW + rb+8];     afL[mi][1] = AsL[tg*SW + rb+8];
            afH[mi][2] = AsH[(tg+4)*SW + rb];   afL[mi][2] = AsL[(tg+4)*SW + rb];
            afH[mi][3] = AsH[(tg+4)*SW + rb+8]; afL[mi][3] = AsL[(tg+4)*SW + rb+8];
        }
        #pragma unroll
        for (int ni = 0; ni < 8; ni++) {
            int cb = wn*64 + ni*8 + g;
            unsigned bH0 = BsH[tg*SW + cb], bH1 = BsH[(tg+4)*SW + cb];
            unsigned bL0 = BsL[tg*SW + cb], bL1 = BsL[(tg+4)*SW + cb];
            #pragma unroll
            for (int mi = 0; mi < 2; mi++) {
                mma_bf16(acc[mi][ni][0], acc[mi][ni][1], acc[mi][ni][2], acc[mi][ni][3],
                         afH[mi][0], afH[mi][1], afH[mi][2], afH[mi][3], bL0, bL1);
                mma_bf16(acc[mi][ni][0], acc[mi][ni][1], acc[mi][ni][2], acc[mi][ni][3],
                         afL[mi][0], afL[mi][1], afL[mi][2], afL[mi][3], bH0, bH1);
                mma_bf16(acc[mi][ni][0], acc[mi][ni][1], acc[mi][ni][2], acc[mi][ni][3],
                         afH[mi][0], afH[mi][1], afH[mi][2], afH[mi][3], bH0, bH1);
            }
        }
        __syncthreads();
    }

    #pragma unroll
    for (int mi = 0; mi < 2; mi++) {
        #pragma unroll
        for (int ni = 0; ni < 8; ni++) {
            size_t iG = (size_t)blockIdx.y*128 + wm*32 + mi*16 + g;
            size_t jG = (size_t)blockIdx.x*128 + wn*64 + ni*8 + tg*2;
            *reinterpret_cast<float2*>(P + ((size_t)bh*SEQ + iG)*SEQ + jG) =
                make_float2(acc[mi][ni][0]*ATT_SCALE, acc[mi][ni][1]*ATT_SCALE);
            *reinterpret_cast<float2*>(P + ((size_t)bh*SEQ + iG + 8)*SEQ + jG) =
                make_float2(acc[mi][ni][2]*ATT_SCALE, acc[mi][ni][3]*ATT_SCALE);
        }
    }
}

// -------- causal row softmax: one warp per row, shuffle-only ---------------
__global__ __launch_bounds__(256)
void softmax_causal(float* __restrict__ P) {
    int w = threadIdx.x >> 5, lane = threadIdx.x & 31;
    int i = blockIdx.x * 8 + w, bh = blockIdx.y;
    int n = i + 1;
    int fillEnd = ((i >> 7) + 1) << 7;
    float* row = P + ((size_t)bh*SEQ + i)*SEQ;
    float lm = -1e30f;
    for (int j = lane; j < n; j += 32) lm = fmaxf(lm, row[j]);
    lm = warp_max(lm);
    float ls = 0.f;
    for (int j = lane; j < n; j += 32) { float e = __expf(row[j] - lm); row[j] = e; ls += e; }
    ls = warp_sum(ls);
    float inv = 1.0f / ls;
    for (int j = lane; j < n; j += 32) row[j] *= inv;
    for (int j = n + lane; j < fillEnd; j += 32) row[j] = 0.f;
}

// -------- knn row softmax: one warp per row; TOPK=32 maps to lanes ---------
__global__ __launch_bounds__(256)
void softmax_knn(float* __restrict__ P, float* __restrict__ TV) {
    int w = threadIdx.x >> 5, lane = threadIdx.x & 31;
    int i = blockIdx.x * 8 + w, bh = blockIdx.y;
    int n = i + 1;
    int fillEnd = ((i >> 7) + 1) << 7;
    float* row = P + ((size_t)bh*SEQ + i)*SEQ;
    float* tvp = TV + ((size_t)bh*SEQ + i)*TOPK;
    float tvv = tvp[lane];
    float lm = tvv;
    for (int j = lane; j < n; j += 32) lm = fmaxf(lm, row[j]);
    lm = warp_max(lm);
    float te = __expf(tvv - lm);
    float ls = te;
    for (int j = lane; j < n; j += 32) { float e = __expf(row[j] - lm); row[j] = e; ls += e; }
    ls = warp_sum(ls);
    float inv = 1.0f / ls;
    for (int j = lane; j < n; j += 32) row[j] *= inv;
    for (int j = n + lane; j < fillEnd; j += 32) row[j] = 0.f;
    tvp[lane] = te * inv;
}

// -------- memory gather: O = sum_t a_mem[t] * MV[idx[t]] -------------------
__global__ __launch_bounds__(64)
void mem_gather(const float* __restrict__ MV, const float* __restrict__ TV,
                const int* __restrict__ TI, float* __restrict__ O) {
    int i = blockIdx.x, bh = blockIdx.y, b = bh >> 3, h = bh & 7;
    int tid = threadIdx.x;
    __shared__ float tv[TOPK];
    __shared__ int   ti[TOPK];
    if (tid < TOPK) {
        tv[tid] = TV[((size_t)bh*SEQ + i)*TOPK + tid];
        ti[tid] = TI[((size_t)bh*SEQ + i)*TOPK + tid];
    }
    __syncthreads();
    const float* mvb = MV + (size_t)b * MEMN * DHEAD;
    float acc = 0.f;
    #pragma unroll
    for (int t = 0; t < TOPK; t++)
        acc += tv[t] * mvb[(size_t)ti[t] * DHEAD + tid];
    O[(size_t)(b*SEQ + i)*DIM + h*DHEAD + tid] = acc;
}

// -------- AV GEMM: O(+)= P[bh] @ V[b,:,h,:]; 128x64 tile, causal-truncated -
#define SWB 72
__global__ __launch_bounds__(256)
void av_tc(const float* __restrict__ P, const float* __restrict__ Vm,
           float* __restrict__ O, int accum) {
    __shared__ unsigned AsH[8*SW], AsL[8*SW];
    __shared__ unsigned BsH[8*SWB], BsL[8*SWB];
    int tid = threadIdx.x, lane = tid & 31, warp = tid >> 5;
    int wm = warp & 3, wn = warp >> 2;
    int g = lane >> 2, tg = lane & 3;
    int by = blockIdx.x, bh = blockIdx.y, b = bh >> 3, h = bh & 7;
    int kmax = (by + 1) * 128;

    int aRow = tid >> 1, aJ0 = (tid & 1) * 4;
    int kp = tid >> 5, col2 = (tid & 31) * 2;

    const float* Ab = P + ((size_t)bh*SEQ + by*128 + aRow)*SEQ + aJ0*2;
    const float* Bb = Vm + (size_t)(b*SEQ + kp*2)*DIM + h*DHEAD + col2;

    float acc[2][4][4];
    #pragma unroll
    for (int mi = 0; mi < 2; mi++)
        #pragma unroll
        for (int ni = 0; ni < 4; ni++)
            #pragma unroll
            for (int r = 0; r < 4; r++) acc[mi][ni][r] = 0.f;

    for (int k0 = 0; k0 < kmax; k0 += 16) {
        float4 a0 = *reinterpret_cast<const float4*>(Ab + k0);
        float4 a1 = *reinterpret_cast<const float4*>(Ab + k0 + 4);
        float af8[8] = {a0.x,a0.y,a0.z,a0.w,a1.x,a1.y,a1.z,a1.w};
        #pragma unroll
        for (int jj = 0; jj < 4; jj++) {
            float x = af8[2*jj], y = af8[2*jj+1];
            float hx = bfhi(x), hy = bfhi(y);
            AsH[(aJ0+jj)*SW + aRow] = bfpack(hx, hy);
            AsL[(aJ0+jj)*SW + aRow] = bfpack(x - hx, y - hy);
        }
        float2 b0 = *reinterpret_cast<const float2*>(Bb + (size_t)k0*DIM);
        float2 b1 = *reinterpret_cast<const float2*>(Bb + (size_t)k0*DIM + DIM);
        {
            float hx = bfhi(b0.x), hy = bfhi(b1.x);
            BsH[kp*SWB + col2]   = bfpack(hx, hy);
            BsL[kp*SWB + col2]   = bfpack(b0.x - hx, b1.x - hy);
            float hx2 = bfhi(b0.y), hy2 = bfhi(b1.y);
            BsH[kp*SWB + col2+1] = bfpack(hx2, hy2);
            BsL[kp*SWB + col2+1] = bfpack(b0.y - hx2, b1.y - hy2);
        }
        __syncthreads();

        unsigned afH[2][4], afL[2][4];
        #pragma unroll
        for (int mi = 0; mi < 2; mi++) {
            int rb = wm*32 + mi*16 + g;
            afH[mi][0] = AsH[tg*SW + rb];       afL[mi][0] = AsL[tg*SW + rb];
            afH[mi][1] = AsH[tg*SW + rb+8];     afL[mi][1] = AsL[tg*SW + rb+8];
            afH[mi][2] = AsH[(tg+4)*SW + rb];   afL[mi][2] = AsL[(tg+4)*SW + rb];
            afH[mi][3] = AsH[(tg+4)*SW + rb+8]; afL[mi][3] = AsL[(tg+4)*SW + rb+8];
        }
        #pragma unroll
        for (int ni = 0; ni < 4; ni++) {
            int cb = wn*32 + ni*8 + g;
            unsigned bH0 = BsH[tg*SWB + cb], bH1 = BsH[(tg+4)*SWB + cb];
            unsigned bL0 = BsL[tg*SWB + cb], bL1 = BsL[(tg+4)*SWB + cb];
            #pragma unroll
            for (int mi = 0; mi < 2; mi++) {
                mma_bf16(acc[mi][ni][0], acc[mi][ni][1], acc[mi][ni][2], acc[mi][ni][3],
                         afH[mi][0], afH[mi][1], afH[mi][2], afH[mi][3], bL0, bL1);
                mma_bf16(acc[mi][ni][0], acc[mi][ni][1], acc[mi][ni][2], acc[mi][ni][3],
                         afL[mi][0], afL[mi][1], afL[mi][2], afL[mi][3], bH0, bH1);
                mma_bf16(acc[mi][ni][0], acc[mi][ni][1], acc[mi][ni][2], acc[mi][ni][3],
                         afH[mi][0], afH[mi][1], afH[mi][2], afH[mi][3], bH0, bH1);
            }
        }
        __syncthreads();
    }

    #pragma unroll
    for (int mi = 0; mi < 2; mi++) {
        #pragma unroll
        for (int ni = 0; ni < 4; ni++) {
            int row = by*128 + wm*32 + mi*16 + g;
            int col = wn*32 + ni*8 + tg*2;
            float* o0 = O + (size_t)(b*SEQ + row)*DIM + h*DHEAD + col;
            float* o1 = O + (size_t)(b*SEQ + row + 8)*DIM + h*DHEAD + col;
            float v0 = acc[mi][ni][0], v1 = acc[mi][ni][1];
            float v2 = acc[mi][ni][2], v3 = acc[mi][ni][3];
            if (accum) {
                float2 r0 = *reinterpret_cast<const float2*>(o0);
                float2 r1 = *reinterpret_cast<const float2*>(o1);
                v0 += r0.x; v1 += r0.y; v2 += r1.x; v3 += r1.y;
            }
            *reinterpret_cast<float2*>(o0) = make_float2(v0, v1);
            *reinterpret_cast<float2*>(o1) = make_float2(v2, v3);
        }
    }
}

// -------- top-32 per (bh,i): smem iterative argmax --------------------------
__global__ __launch_bounds__(256)
void topk_kernel(const float* __restrict__ S, float* __restrict__ TV,
                 int* __restrict__ TI) {
    int i = blockIdx.x, bh = blockIdx.y;
    const float* row = S + ((size_t)bh*SEQ + i)*MEMN;
    __shared__ float sv[MEMN];
    __shared__ float wv[8];
    __shared__ int   wi[8];
    __shared__ int wini;
    int tid = threadIdx.x;

    float lmax = -1e30f; int lidx = 0;
    #pragma unroll 4
    for (int j = 0; j < 16; j++) {
        int m = tid + 256*j;
        float v = row[m];
        sv[m] = v;
        if (v > lmax) { lmax = v; lidx = m; }
    }
    for (int t = 0; t < TOPK; t++) {
        float v = lmax; int idx = lidx;
        #pragma unroll
        for (int o = 16; o > 0; o >>= 1) {
            float ov = __shfl_xor_sync(0xffffffffu, v, o);
            int   oi = __shfl_xor_sync(0xffffffffu, idx, o);
            if (ov > v) { v = ov; idx = oi; }
        }
        if ((tid & 31) == 0) { wv[tid>>5] = v; wi[tid>>5] = idx; }
        __syncthreads();
        if (tid < 32) {
            float v2 = (tid < 8) ? wv[tid] : -1e30f;
            int   i2 = (tid < 8) ? wi[tid] : 0;
            #pragma unroll
            for (int o = 4; o > 0; o >>= 1) {
                float ov = __shfl_xor_sync(0xffffffffu, v2, o);
                int   oi = __shfl_xor_sync(0xffffffffu, i2, o);
                if (ov > v2) { v2 = ov; i2 = oi; }
            }
            if (tid == 0) {
                wini = i2;
                TV[((size_t)bh*SEQ + i)*TOPK + t] = v2;
                TI[((size_t)bh*SEQ + i)*TOPK + t] = i2;
            }
        }
        __syncthreads();
        int widx = wini;
        if ((widx & 255) == tid) {
            sv[widx] = -1e30f;
            lmax = -1e30f; lidx = 0;
            #pragma unroll 4
            for (int j = 0; j < 16; j++) {
                int m = tid + 256*j;
                float vv = sv[m];
                if (vv > lmax) { lmax = vv; lidx = m; }
            }
        }
    }
}

// ---------------- host orchestration --------------------------------------
extern "C" void kernel_launch(void* const* d_in, const int* in_sizes, int n_in,
                              void* d_out, int out_size) {
    const float* x     = (const float*)d_in[0];
    const float* Wq    = (const float*)d_in[1];
    const float* Wk    = (const float*)d_in[2];
    const float* Wv    = (const float*)d_in[3];
    const float* Wo    = (const float*)d_in[4];
    const float* ln1s  = (const float*)d_in[5];
    const float* ln1b  = (const float*)d_in[6];
    const float* ln2s  = (const float*)d_in[7];
    const float* ln2b  = (const float*)d_in[8];
    const float* W1    = (const float*)d_in[9];
    const float* W2    = (const float*)d_in[10];
    const float* lnfs  = (const float*)d_in[11];
    const float* lnfb  = (const float*)d_in[12];
    const float* mem_k = (const float*)d_in[13];
    const float* mem_v = (const float*)d_in[14];

    float *X, *H, *Q, *K, *V, *AO, *FFb, *S, *P, *TV;
    int *TI; unsigned *WH, *WL;
    cudaGetSymbolAddress((void**)&X,  g_X);
    cudaGetSymbolAddress((void**)&H,  g_H);
    cudaGetSymbolAddress((void**)&Q,  g_Q);
    cudaGetSymbolAddress((void**)&K,  g_K);
    cudaGetSymbolAddress((void**)&V,  g_V);
    cudaGetSymbolAddress((void**)&AO, g_AO);
    cudaGetSymbolAddress((void**)&FFb, g_FF);
    cudaGetSymbolAddress((void**)&S,  g_S);
    cudaGetSymbolAddress((void**)&P,  g_P);
    cudaGetSymbolAddress((void**)&TV, g_TV);
    cudaGetSymbolAddress((void**)&TI, g_TI);
    cudaGetSymbolAddress((void**)&WH, g_WH);
    cudaGetSymbolAddress((void**)&WL, g_WL);

    cudaMemcpyAsync(X, x, sizeof(float) * MROWS * DIM, cudaMemcpyDeviceToDevice);

    const int OQ = 0, OK = 6*PQ, OV = 12*PQ, OO = 18*PQ, O1 = 24*PQ, O2 = 24*PQ + 6*PF;
    split_w<<<dim3(PQ/256, DEPTH), 256>>>(Wq, WH + OQ, WL + OQ, PQ, DIM);
    split_w<<<dim3(PQ/256, DEPTH), 256>>>(Wk, WH + OK, WL + OK, PQ, DIM);
    split_w<<<dim3(PQ/256, DEPTH), 256>>>(Wv, WH + OV, WL + OV, PQ, DIM);
    split_w<<<dim3(PQ/256, DEPTH), 256>>>(Wo, WH + OO, WL + OO, PQ, DIM);
    split_w<<<dim3(PF/256, DEPTH), 256>>>(W1, WH + O1, WL + O1, PF, FFDIM);
    split_w<<<dim3(PF/256, DEPTH), 256>>>(W2, WH + O2, WL + O2, PF, DIM);

    dim3 gD(DIM/128, MROWS/128);          // 4 x 32
    dim3 gQKV(DIM/128, MROWS/128, 3);
    dim3 gF(FFDIM/128, MROWS/128);        // 16 x 32
    dim3 gSim(MEMN/128, SEQ/128, NBH);
    dim3 gLoc(SEQ/128, SEQ/128, NBH);
    dim3 gRow(SEQ, NBH);
    dim3 gSm(SEQ/8, NBH);                 // warp-per-row softmax
    dim3 gAV(MROWS/128 / BATCH, NBH);

    int mi = 0;
    for (int l = 0; l < DEPTH; l++) {
        ln_kernel<<<MROWS, 128>>>(X, ln1s + l*DIM, ln1b + l*DIM, H);
        gemm_qkv<<<gQKV, 128>>>(H, WH, WL, OQ + l*PQ, OK + l*PQ, OV + l*PQ, Q, K, V);
        if (l == 3 || l == 4) {
            const float* MK = mem_k + (size_t)mi * BATCH * MEMN * DHEAD;
            const float* MV = mem_v + (size_t)mi * BATCH * MEMN * DHEAD;
            knn_sim_tc<<<gSim, 256>>>(Q, MK, S);
            topk_kernel<<<gRow, 256>>>(S, TV, TI);
            sim_local_tc<<<gLoc, 256>>>(Q, K, P);
            softmax_knn<<<gSm, 256>>>(P, TV);
            mem_gather<<<gRow, 64>>>(MV, TV, TI, AO);
            av_tc<<<gAV, 256>>>(P, V, AO, 1);
            mi++;
        } else {
            sim_local_tc<<<gLoc, 256>>>(Q, K, P);
            softmax_causal<<<gSm, 256>>>(P);
            av_tc<<<gAV, 256>>>(P, V, AO, 0);
        }
        gemm_tc<<<gD, 128>>>(AO, WH + OO + l*PQ, WL + OO + l*PQ, X, X, DIM, DIM, 0);
        ln_kernel<<<MROWS, 128>>>(X, ln2s + l*DIM, ln2b + l*DIM, H);
        gemm_tc<<<gF, 128>>>(H, WH + O1 + l*PF, WL + O1 + l*PF, nullptr, FFb, FFDIM, DIM, 1);
        gemm_tc<<<gD, 128>>>(FFb, WH + O2 + l*PF, WL + O2 + l*PF, X, X, DIM, FFDIM, 0);
    }
    ln_kernel<<<MROWS, 128>>>(X, lnfs, lnfb, (float*)d_out);
}